// round 1
// baseline (speedup 1.0000x reference)
#include <cuda_runtime.h>

#define NB 32
#define NL 100
#define NT (NB*NL)      // 3200 tokens
#define ND 200
#define INDIM 360
#define EMBD 300
#define POSD 30
#define NERD 30
#define NREL 40
#define TT 32           // tokens per block in GEMM kernels
#define LTILE 4         // l rows per block in agg kernel

__device__ float g_xa[NT*ND];
__device__ float g_xb[NT*ND];
__device__ float g_z[NT*ND];
__device__ float g_invden[NT];

// ---------------------------------------------------------------------------
// denom + mask: rowcount/colcount of nonzero adj entries per b
// ---------------------------------------------------------------------------
__global__ void denom_mask_kernel(const int* __restrict__ adj,
                                  float* __restrict__ out_mask,
                                  int write_mask) {
    int b = blockIdx.x;
    __shared__ int rowc[NL], colc[NL];
    int tid = threadIdx.x;
    if (tid < NL) {
        int rc = 0;
        const int* row = adj + (b*NL + tid)*NL;
        #pragma unroll 4
        for (int m = 0; m < NL; m++) rc += (row[m] != 0);
        rowc[tid] = rc;
        int cc = 0;
        for (int l = 0; l < NL; l++) cc += (adj[(b*NL + l)*NL + tid] != 0);
        colc[tid] = cc;
    }
    __syncthreads();
    if (tid < NL) {
        g_invden[b*NL + tid] = 1.0f / (float)(rowc[tid] + 1);
        if (write_mask)
            out_mask[b*NL + tid] = (rowc[tid] + colc[tid] == 0) ? 1.0f : 0.0f;
    }
}

// ---------------------------------------------------------------------------
// Embedding gather + preprocessor GEMM: x0[t,j] = concat_embs(t) . Wp[j,:] + bp[j]
// Block: 32 tokens x 200 outputs. 256 thr = 32 lanes(tokens) x 8 warps(25 j each).
// k staged in 32-wide smem chunks (gathered on the fly per chunk).
// ---------------------------------------------------------------------------
__global__ void embed_gemm_kernel(const int* __restrict__ words,
                                  const int* __restrict__ pos,
                                  const int* __restrict__ ner,
                                  const float* __restrict__ emb,
                                  const float* __restrict__ pos_emb,
                                  const float* __restrict__ ner_emb,
                                  const float* __restrict__ Wp,
                                  const float* __restrict__ bp,
                                  float* __restrict__ xout) {
    __shared__ float Es[TT*33];
    __shared__ float Ws[ND*33];
    int tid = threadIdx.x;
    int lane = tid & 31, w = tid >> 5;
    int t0 = blockIdx.x * TT;
    float acc[25];
    #pragma unroll
    for (int i = 0; i < 25; i++) acc[i] = 0.f;

    for (int kc = 0; kc < INDIM; kc += 32) {
        int kw = min(32, INDIM - kc);
        for (int idx = tid; idx < TT*kw; idx += blockDim.x) {
            int tl = idx / kw, kk = idx - tl*kw;
            int k = kc + kk;
            int tok = t0 + tl;
            float v;
            if (k < EMBD)            v = emb[words[tok]*EMBD + k];
            else if (k < EMBD+POSD)  v = pos_emb[pos[tok]*POSD + (k - EMBD)];
            else                     v = ner_emb[ner[tok]*NERD + (k - EMBD - POSD)];
            Es[tl*33 + kk] = v;
        }
        for (int idx = tid; idx < ND*kw; idx += blockDim.x) {
            int j = idx / kw, kk = idx - j*kw;
            Ws[j*33 + kk] = Wp[j*INDIM + kc + kk];
        }
        __syncthreads();
        for (int kk = 0; kk < kw; kk++) {
            float zv = Es[lane*33 + kk];
            #pragma unroll
            for (int i = 0; i < 25; i++)
                acc[i] += zv * Ws[(w*25 + i)*33 + kk];
        }
        __syncthreads();
    }
    int tok = t0 + lane;
    #pragma unroll
    for (int i = 0; i < 25; i++) {
        int j = w*25 + i;
        xout[tok*ND + j] = acc[i] + bp[j];
    }
}

// ---------------------------------------------------------------------------
// Aggregation: Z[b,l,d] = x[b,l,d] + sum_m E[adj[b,l,m], d] * x[b,m,d]
// Relation table (40x200 = 32KB) in smem; LTILE=4 l-rows per block share the
// streamed x[b,m,:] reads. Grid (25, 32), 256 threads (d = tid, 200 active).
// ---------------------------------------------------------------------------
__global__ void agg_kernel(const int* __restrict__ adj,
                           const float* __restrict__ dep,
                           const float* __restrict__ x,
                           float* __restrict__ z) {
    __shared__ float Es[NREL*ND];      // 32 KB
    __shared__ int adjs[LTILE*NL];
    int tid = threadIdx.x;
    int b = blockIdx.y;
    int l0 = blockIdx.x * LTILE;
    for (int i = tid; i < NREL*ND; i += blockDim.x) Es[i] = dep[i];
    for (int i = tid; i < LTILE*NL; i += blockDim.x)
        adjs[i] = adj[(b*NL + l0 + i/NL)*NL + (i % NL)];
    __syncthreads();

    int d = tid;
    if (d < ND) {
        float acc[LTILE];
        #pragma unroll
        for (int i = 0; i < LTILE; i++)
            acc[i] = x[(b*NL + l0 + i)*ND + d];
        const float* xb = x + b*NL*ND;
        for (int m = 0; m < NL; m++) {
            float xv = xb[m*ND + d];
            #pragma unroll
            for (int i = 0; i < LTILE; i++) {
                int r = adjs[i*NL + m];
                acc[i] += Es[r*ND + d] * xv;
            }
        }
        #pragma unroll
        for (int i = 0; i < LTILE; i++)
            z[(b*NL + l0 + i)*ND + d] = acc[i];
    }
}

// ---------------------------------------------------------------------------
// GEMM + bias + /denom + relu:  out[t,j] = relu((Z[t,:].W[j,:] + 2*b[j]) * invden[t])
// Same 32-token x 200-output tiling as embed_gemm_kernel, K=200.
// ---------------------------------------------------------------------------
__global__ void gemm_relu_kernel(const float* __restrict__ zin,
                                 const float* __restrict__ Wm,
                                 const float* __restrict__ bias,
                                 float* __restrict__ xout) {
    __shared__ float Zs[TT*33];
    __shared__ float Ws[ND*33];
    int tid = threadIdx.x;
    int lane = tid & 31, w = tid >> 5;
    int t0 = blockIdx.x * TT;
    float acc[25];
    #pragma unroll
    for (int i = 0; i < 25; i++) acc[i] = 0.f;

    for (int kc = 0; kc < ND; kc += 32) {
        int kw = min(32, ND - kc);
        for (int idx = tid; idx < TT*kw; idx += blockDim.x) {
            int tl = idx / kw, kk = idx - tl*kw;
            Zs[tl*33 + kk] = zin[(t0 + tl)*ND + kc + kk];
        }
        for (int idx = tid; idx < ND*kw; idx += blockDim.x) {
            int j = idx / kw, kk = idx - j*kw;
            Ws[j*33 + kk] = Wm[j*ND + kc + kk];
        }
        __syncthreads();
        for (int kk = 0; kk < kw; kk++) {
            float zv = Zs[lane*33 + kk];
            #pragma unroll
            for (int i = 0; i < 25; i++)
                acc[i] += zv * Ws[(w*25 + i)*33 + kk];
        }
        __syncthreads();
    }
    int tok = t0 + lane;
    float inv = g_invden[tok];
    #pragma unroll
    for (int i = 0; i < 25; i++) {
        int j = w*25 + i;
        float v = (acc[i] + 2.f*bias[j]) * inv;
        xout[tok*ND + j] = fmaxf(v, 0.f);
    }
}

// ---------------------------------------------------------------------------
extern "C" void kernel_launch(void* const* d_in, const int* in_sizes, int n_in,
                              void* d_out, int out_size) {
    const int*   adj     = (const int*)  d_in[0];
    const int*   words   = (const int*)  d_in[1];
    const int*   pos     = (const int*)  d_in[2];
    const int*   ner     = (const int*)  d_in[3];
    const float* emb     = (const float*)d_in[4];
    const float* pos_emb = (const float*)d_in[5];
    const float* ner_emb = (const float*)d_in[6];
    const float* dep     = (const float*)d_in[7];
    const float* Wp      = (const float*)d_in[8];
    const float* bp      = (const float*)d_in[9];
    const float* W0      = (const float*)d_in[10];
    const float* b0      = (const float*)d_in[11];
    const float* W1      = (const float*)d_in[12];
    const float* b1      = (const float*)d_in[13];
    float* out = (float*)d_out;

    float *xa, *xb, *z;
    cudaGetSymbolAddress((void**)&xa, g_xa);
    cudaGetSymbolAddress((void**)&xb, g_xb);
    cudaGetSymbolAddress((void**)&z,  g_z);

    int write_mask = (out_size >= NT*ND + NT) ? 1 : 0;

    denom_mask_kernel<<<NB, 128>>>(adj, out + NT*ND, write_mask);
    embed_gemm_kernel<<<NT/TT, 256>>>(words, pos, ner, emb, pos_emb, ner_emb,
                                      Wp, bp, xa);
    agg_kernel<<<dim3(NL/LTILE, NB), 256>>>(adj, dep, xa, z);
    gemm_relu_kernel<<<NT/TT, 256>>>(z, W0, b0, xb);
    agg_kernel<<<dim3(NL/LTILE, NB), 256>>>(adj, dep, xb, z);
    gemm_relu_kernel<<<NT/TT, 256>>>(z, W1, b1, out);
}

// round 2
// speedup vs baseline: 2.2102x; 2.2102x over previous
#include <cuda_runtime.h>

#define NB 32
#define NL 100
#define NT (NB*NL)      // 3200 tokens
#define ND 200
#define INDIM 360
#define EMBD 300
#define POSD 30
#define NERD 30
#define NREL 40
#define LTILE 4

#define BM 64           // tokens per block tile
#define BN 64           // outputs per block tile
#define KC 16           // k chunk

__device__ float g_xa[NT*INDIM];   // gathered concat embeddings
__device__ float g_xb[NT*ND];
__device__ float g_xc[NT*ND];
__device__ float g_z[NT*ND];
__device__ float g_invden[NT];

// ---------------------------------------------------------------------------
// denom + mask
// ---------------------------------------------------------------------------
__global__ void denom_mask_kernel(const int* __restrict__ adj,
                                  float* __restrict__ out_mask,
                                  int write_mask) {
    int b = blockIdx.x;
    __shared__ int rowc[NL], colc[NL];
    int tid = threadIdx.x;
    if (tid < NL) {
        int rc = 0;
        const int* row = adj + (b*NL + tid)*NL;
        #pragma unroll 4
        for (int m = 0; m < NL; m++) rc += (row[m] != 0);
        rowc[tid] = rc;
        int cc = 0;
        for (int l = 0; l < NL; l++) cc += (adj[(b*NL + l)*NL + tid] != 0);
        colc[tid] = cc;
    }
    __syncthreads();
    if (tid < NL) {
        g_invden[b*NL + tid] = 1.0f / (float)(rowc[tid] + 1);
        if (write_mask)
            out_mask[b*NL + tid] = (rowc[tid] + colc[tid] == 0) ? 1.0f : 0.0f;
    }
}

// ---------------------------------------------------------------------------
// Embedding gather: one block per token, 384 threads, concat into [NT][INDIM]
// ---------------------------------------------------------------------------
__global__ void gather_kernel(const int* __restrict__ words,
                              const int* __restrict__ pos,
                              const int* __restrict__ ner,
                              const float* __restrict__ emb,
                              const float* __restrict__ pos_emb,
                              const float* __restrict__ ner_emb,
                              float* __restrict__ xout) {
    int tok = blockIdx.x;
    int k = threadIdx.x;
    if (k >= INDIM) return;
    float v;
    if (k < EMBD)            v = emb[words[tok]*EMBD + k];
    else if (k < EMBD+POSD)  v = pos_emb[pos[tok]*POSD + (k - EMBD)];
    else                     v = ner_emb[ner[tok]*NERD + (k - EMBD - POSD)];
    xout[tok*INDIM + k] = v;
}

// ---------------------------------------------------------------------------
// Register-tiled SGEMM: C[M x 200] = A[M x K] . B[200 x K]^T  (+ epilogue)
// Block tile 64x64, 256 threads, 4x4 per thread, k-major smem + LDS.128.
// MODE 0: C = acc + bias[j]
// MODE 1: C = relu((acc + 2*bias[j]) * invden[t])
// ---------------------------------------------------------------------------
template<int K, int MODE>
__global__ void gemm_kernel(const float* __restrict__ A,
                            const float* __restrict__ B,
                            const float* __restrict__ bias,
                            float* __restrict__ C) {
    __shared__ float As[KC][BM+4];
    __shared__ float Bs[KC][BN+4];
    int tid = threadIdx.x;
    int tx = tid & 15;          // token group (4 tokens each)
    int ty = tid >> 4;          // j group (4 j each)
    int t0 = blockIdx.x * BM;
    int j0 = blockIdx.y * BN;

    float acc[4][4];
    #pragma unroll
    for (int i = 0; i < 4; i++)
        #pragma unroll
        for (int j = 0; j < 4; j++) acc[i][j] = 0.f;

    for (int kc = 0; kc < K; kc += KC) {
        int kw = K - kc; if (kw > KC) kw = KC;
        // load A chunk (transpose to k-major), zero-fill beyond kw
        #pragma unroll
        for (int it = 0; it < (BM*KC)/256; it++) {
            int idx = tid + it*256;
            int kk = idx & (KC-1);
            int t  = idx >> 4;
            As[kk][t] = (kk < kw) ? A[(t0 + t)*K + kc + kk] : 0.f;
        }
        // load B chunk, guard j<ND
        #pragma unroll
        for (int it = 0; it < (BN*KC)/256; it++) {
            int idx = tid + it*256;
            int kk = idx & (KC-1);
            int j  = idx >> 4;
            Bs[kk][j] = (kk < kw && (j0 + j) < ND) ? B[(j0 + j)*K + kc + kk] : 0.f;
        }
        __syncthreads();
        #pragma unroll
        for (int kk = 0; kk < KC; kk++) {
            float4 a = *(const float4*)&As[kk][4*tx];
            float4 b = *(const float4*)&Bs[kk][4*ty];
            acc[0][0] += a.x*b.x; acc[0][1] += a.x*b.y; acc[0][2] += a.x*b.z; acc[0][3] += a.x*b.w;
            acc[1][0] += a.y*b.x; acc[1][1] += a.y*b.y; acc[1][2] += a.y*b.z; acc[1][3] += a.y*b.w;
            acc[2][0] += a.z*b.x; acc[2][1] += a.z*b.y; acc[2][2] += a.z*b.z; acc[2][3] += a.z*b.w;
            acc[3][0] += a.w*b.x; acc[3][1] += a.w*b.y; acc[3][2] += a.w*b.z; acc[3][3] += a.w*b.w;
        }
        __syncthreads();
    }

    int tbase = t0 + 4*tx;
    int jbase = j0 + 4*ty;
    #pragma unroll
    for (int i = 0; i < 4; i++) {
        int tok = tbase + i;
        float inv = (MODE == 1) ? g_invden[tok] : 0.f;
        #pragma unroll
        for (int j = 0; j < 4; j++) {
            int jj = jbase + j;
            if (jj < ND) {
                float v;
                if (MODE == 0) v = acc[i][j] + bias[jj];
                else {
                    v = (acc[i][j] + 2.f*bias[jj]) * inv;
                    v = fmaxf(v, 0.f);
                }
                C[tok*ND + jj] = v;
            }
        }
    }
}

// ---------------------------------------------------------------------------
// Aggregation: Z[b,l,d] = x[b,l,d] + sum_m E[adj[b,l,m], d] * x[b,m,d]
// Relation table in smem; adj entries cached pre-multiplied by ND.
// ---------------------------------------------------------------------------
__global__ void agg_kernel(const int* __restrict__ adj,
                           const float* __restrict__ dep,
                           const float* __restrict__ x,
                           float* __restrict__ z) {
    __shared__ float Es[NREL*ND];      // 32 KB
    __shared__ int adjs[LTILE*NL];
    int tid = threadIdx.x;
    int b = blockIdx.y;
    int l0 = blockIdx.x * LTILE;
    for (int i = tid; i < NREL*ND; i += blockDim.x) Es[i] = dep[i];
    for (int i = tid; i < LTILE*NL; i += blockDim.x)
        adjs[i] = adj[(b*NL + l0 + i/NL)*NL + (i % NL)] * ND;
    __syncthreads();

    int d = tid;
    if (d < ND) {
        float acc[LTILE];
        #pragma unroll
        for (int i = 0; i < LTILE; i++)
            acc[i] = x[(b*NL + l0 + i)*ND + d];
        const float* xb = x + b*NL*ND;
        #pragma unroll 2
        for (int m = 0; m < NL; m++) {
            float xv = xb[m*ND + d];
            #pragma unroll
            for (int i = 0; i < LTILE; i++) {
                int r = adjs[i*NL + m];
                acc[i] += Es[r + d] * xv;
            }
        }
        #pragma unroll
        for (int i = 0; i < LTILE; i++)
            z[(b*NL + l0 + i)*ND + d] = acc[i];
    }
}

// ---------------------------------------------------------------------------
extern "C" void kernel_launch(void* const* d_in, const int* in_sizes, int n_in,
                              void* d_out, int out_size) {
    const int*   adj     = (const int*)  d_in[0];
    const int*   words   = (const int*)  d_in[1];
    const int*   pos     = (const int*)  d_in[2];
    const int*   ner     = (const int*)  d_in[3];
    const float* emb     = (const float*)d_in[4];
    const float* pos_emb = (const float*)d_in[5];
    const float* ner_emb = (const float*)d_in[6];
    const float* dep     = (const float*)d_in[7];
    const float* Wp      = (const float*)d_in[8];
    const float* bp      = (const float*)d_in[9];
    const float* W0      = (const float*)d_in[10];
    const float* b0      = (const float*)d_in[11];
    const float* W1      = (const float*)d_in[12];
    const float* b1      = (const float*)d_in[13];
    float* out = (float*)d_out;

    float *xa, *xb, *xc, *z;
    cudaGetSymbolAddress((void**)&xa, g_xa);
    cudaGetSymbolAddress((void**)&xb, g_xb);
    cudaGetSymbolAddress((void**)&xc, g_xc);
    cudaGetSymbolAddress((void**)&z,  g_z);

    int write_mask = (out_size >= NT*ND + NT) ? 1 : 0;

    dim3 ggrid(NT/BM, (ND + BN - 1)/BN);   // (50, 4)

    gather_kernel<<<NT, 384>>>(words, pos, ner, emb, pos_emb, ner_emb, xa);
    denom_mask_kernel<<<NB, 128>>>(adj, out + NT*ND, write_mask);
    gemm_kernel<INDIM, 0><<<ggrid, 256>>>(xa, Wp, bp, xb);
    agg_kernel<<<dim3(NL/LTILE, NB), 256>>>(adj, dep, xb, z);
    gemm_kernel<ND, 1><<<ggrid, 256>>>(z, W0, b0, xc);
    agg_kernel<<<dim3(NL/LTILE, NB), 256>>>(adj, dep, xc, z);
    gemm_kernel<ND, 1><<<ggrid, 256>>>(z, W1, b1, out);
}